// round 10
// baseline (speedup 1.0000x reference)
#include <cuda_runtime.h>

// GEMV: out[1, 8192] = x[1, 8192] @ W[8192, 8192] + b
// d_in[0]=x (8192 f32), d_in[1]=W (8192x8192 f32 row-major), d_in[2]=b.
//
// Single-node fused split-K GEMV. R8's race: __threadfence() only orders the
// CALLING thread's atomics; tid0 could bump the tile counter while other
// lanes' RED.F32 partial-adds were still in flight. Fix: per-thread fence,
// then __syncthreads(), THEN tid0 increments the counter -- the bar gives
// happens-before between every lane's fence and tid0's increment, so the
// last-arriving block observes all 64 splits' partials in L2.
// Scratch + counters are __device__ globals (zero at load) and are restored
// to zero by the last block, keeping every graph replay identical.

static constexpr int IN_LEN  = 8192;
static constexpr int OUT_LEN = 8192;

static constexpr int THREADS        = 128;
static constexpr int COLS_PER_BLOCK = THREADS * 4;               // 512
static constexpr int COL_BLOCKS     = OUT_LEN / COLS_PER_BLOCK;  // 16
static constexpr int ROWS_PER_SPLIT = 128;
static constexpr int ROW_SPLITS     = IN_LEN / ROWS_PER_SPLIT;   // 64
// grid = 16 x 64 = 1024 blocks -> single wave (best measured geometry).

__device__ float        g_scratch[OUT_LEN];     // zero at load; self-cleaning
__device__ unsigned int g_count[COL_BLOCKS];    // zero at load; self-cleaning

__global__ __launch_bounds__(THREADS, 7)
void dense_gemv_fused(const float* __restrict__ x,
                      const float* __restrict__ W,
                      const float* __restrict__ b,
                      float* __restrict__ out) {
    const int cb   = blockIdx.x;
    const int col0 = cb * COLS_PER_BLOCK + threadIdx.x * 4;
    const int row0 = blockIdx.y * ROWS_PER_SPLIT;

    __shared__ float xs[ROWS_PER_SPLIT];
    xs[threadIdx.x] = x[row0 + threadIdx.x];
    __syncthreads();

    const float4* __restrict__ Wp =
        reinterpret_cast<const float4*>(W + (size_t)row0 * OUT_LEN + col0);
    const size_t row_stride_v4 = OUT_LEN / 4;

    float4 acc = make_float4(0.f, 0.f, 0.f, 0.f);

    #pragma unroll 16
    for (int i = 0; i < ROWS_PER_SPLIT; i++) {
        const float xv = xs[i];
        const float4 w = Wp[(size_t)i * row_stride_v4];
        acc.x = fmaf(xv, w.x, acc.x);
        acc.y = fmaf(xv, w.y, acc.y);
        acc.z = fmaf(xv, w.z, acc.z);
        acc.w = fmaf(xv, w.w, acc.w);
    }

    // Publish this split's partial (L2 atomics, 8192 spread addresses).
    atomicAdd(&g_scratch[col0 + 0], acc.x);
    atomicAdd(&g_scratch[col0 + 1], acc.y);
    atomicAdd(&g_scratch[col0 + 2], acc.z);
    atomicAdd(&g_scratch[col0 + 3], acc.w);

    // Make THIS thread's adds device-visible, then barrier so tid0's counter
    // increment happens-after every lane's fence (this was the R8 race).
    __threadfence();
    __syncthreads();

    __shared__ bool is_last;
    if (threadIdx.x == 0) {
        unsigned int prev = atomicAdd(&g_count[cb], 1u);
        is_last = (prev == (unsigned int)(ROW_SPLITS - 1));
    }
    __syncthreads();

    if (is_last) {
        // All 64 splits for this tile are visible in L2. Read via L2
        // (bypass L1), add bias, emit, restore scratch/counter to zero.
        const float4 bb = *reinterpret_cast<const float4*>(b + col0);
        float4 s;
        s.x = __ldcg(&g_scratch[col0 + 0]) + bb.x;
        s.y = __ldcg(&g_scratch[col0 + 1]) + bb.y;
        s.z = __ldcg(&g_scratch[col0 + 2]) + bb.z;
        s.w = __ldcg(&g_scratch[col0 + 3]) + bb.w;
        *reinterpret_cast<float4*>(out + col0) = s;

        g_scratch[col0 + 0] = 0.f;
        g_scratch[col0 + 1] = 0.f;
        g_scratch[col0 + 2] = 0.f;
        g_scratch[col0 + 3] = 0.f;
        if (threadIdx.x == 0) g_count[cb] = 0u;
    }
}

extern "C" void kernel_launch(void* const* d_in, const int* in_sizes, int n_in,
                              void* d_out, int out_size) {
    const float* x = (const float*)d_in[0];
    const float* W = (const float*)d_in[1];
    const float* b = (const float*)d_in[2];
    float* out = (float*)d_out;

    dim3 grid(COL_BLOCKS, ROW_SPLITS);
    dense_gemv_fused<<<grid, THREADS>>>(x, W, b, out);
}

// round 12
// speedup vs baseline: 1.0391x; 1.0391x over previous
#include <cuda_runtime.h>

// GEMV: out[1, 8192] = x[1, 8192] @ W[8192, 8192] + b
// d_in[0]=x (8192 f32), d_in[1]=W (8192x8192 f32 row-major), d_in[2]=b.
//
// R10: revert the fused single-node combine (fence epilogue cost ~2.4us in
// kernel > ~1.5us node savings). Structure: graph memcpy node seeds out with
// the bias (32KB d2d), then the best-measured gemv geometry (16x64 = 1024
// blocks, single wave, unroll 16, 7-CTA bound) atomicAdds split-K partials
// directly into out. New isolated variable: __ldcs on the W stream (read
// exactly once, 2x L2 capacity -> evict-first).

static constexpr int IN_LEN  = 8192;
static constexpr int OUT_LEN = 8192;

static constexpr int THREADS        = 128;
static constexpr int COLS_PER_BLOCK = THREADS * 4;               // 512
static constexpr int COL_BLOCKS     = OUT_LEN / COLS_PER_BLOCK;  // 16
static constexpr int ROWS_PER_SPLIT = 128;
static constexpr int ROW_SPLITS     = IN_LEN / ROWS_PER_SPLIT;   // 64
// grid = 16 x 64 = 1024 blocks -> single wave (best measured geometry).

__global__ __launch_bounds__(THREADS, 7)
void dense_gemv_splitk(const float* __restrict__ x,
                       const float* __restrict__ W,
                       float* __restrict__ out) {
    const int col0 = blockIdx.x * COLS_PER_BLOCK + threadIdx.x * 4;
    const int row0 = blockIdx.y * ROWS_PER_SPLIT;

    __shared__ float xs[ROWS_PER_SPLIT];
    xs[threadIdx.x] = x[row0 + threadIdx.x];
    __syncthreads();

    const float4* __restrict__ Wp =
        reinterpret_cast<const float4*>(W + (size_t)row0 * OUT_LEN + col0);
    const size_t row_stride_v4 = OUT_LEN / 4;

    float4 acc = make_float4(0.f, 0.f, 0.f, 0.f);

    // 16 independent streaming LDG.128 per body; evict-first since W has
    // zero reuse (256MB read-once stream vs 126MB L2).
    #pragma unroll 16
    for (int i = 0; i < ROWS_PER_SPLIT; i++) {
        const float xv = xs[i];
        const float4 w = __ldcs(&Wp[(size_t)i * row_stride_v4]);
        acc.x = fmaf(xv, w.x, acc.x);
        acc.y = fmaf(xv, w.y, acc.y);
        acc.z = fmaf(xv, w.z, acc.z);
        acc.w = fmaf(xv, w.w, acc.w);
    }

    // out is pre-seeded with the bias by the memcpy node; 64 RED.F32 per
    // output address, spread across 8192 addresses -> hidden.
    atomicAdd(&out[col0 + 0], acc.x);
    atomicAdd(&out[col0 + 1], acc.y);
    atomicAdd(&out[col0 + 2], acc.z);
    atomicAdd(&out[col0 + 3], acc.w);
}

extern "C" void kernel_launch(void* const* d_in, const int* in_sizes, int n_in,
                              void* d_out, int out_size) {
    const float* x = (const float*)d_in[0];
    const float* W = (const float*)d_in[1];
    const float* b = (const float*)d_in[2];
    float* out = (float*)d_out;

    // Seed out with the bias (graph memcpy node, d2d, capture-legal).
    cudaMemcpyAsync(out, b, OUT_LEN * sizeof(float), cudaMemcpyDeviceToDevice);

    dim3 grid(COL_BLOCKS, ROW_SPLITS);
    dense_gemv_splitk<<<grid, THREADS>>>(x, W, out);
}